// round 10
// baseline (speedup 1.0000x reference)
#include <cuda_runtime.h>
#include <math.h>

// Problem constants (fixed shapes for this dataset entry)
#define MAXN   50000
#define F      256     // feature dim
#define D      64      // neighbors per node
#define KSEL   8       // top-k
#define H      8       // heads
#define O      32      // out per head
#define HO     256     // H*O
#define NEG_SLOPE 0.2f

// ---------------- scratch (device globals; no allocations allowed) ----------
__device__ float g_y[MAXN];
__device__ float g_ft[(size_t)MAXN * HO];
__device__ float g_el[MAXN * H];
__device__ float g_er[MAXN * H];
__device__ float g_inv_pnorm;

// ---------------- f32x2 packed-FMA helpers (Blackwell fma.rn.f32x2) ---------
__device__ __forceinline__ unsigned long long ffma2(unsigned long long a,
                                                    unsigned long long b,
                                                    unsigned long long c) {
    unsigned long long d;
    asm volatile("fma.rn.f32x2 %0, %1, %2, %3;" : "=l"(d) : "l"(a), "l"(b), "l"(c));
    return d;
}
__device__ __forceinline__ unsigned long long pack2(float x) {
    unsigned long long r;
    unsigned int u = __float_as_uint(x);
    asm("mov.b64 %0, {%1, %1};" : "=l"(r) : "r"(u));
    return r;
}
__device__ __forceinline__ float2 unpack2(unsigned long long v) {
    unsigned int lo, hi;
    asm("mov.b64 {%0, %1}, %2;" : "=r"(lo), "=r"(hi) : "l"(v));
    return make_float2(__uint_as_float(lo), __uint_as_float(hi));
}

// ---------------- K0: 1/||p|| -----------------------------------------------
__global__ void pnorm_kernel(const float* __restrict__ p) {
    __shared__ float sh[256];
    int t = threadIdx.x;
    float v = p[t];
    v = v * v;
    sh[t] = v;
    __syncthreads();
    for (int s = 128; s > 0; s >>= 1) {
        if (t < s) sh[t] += sh[t + s];
        __syncthreads();
    }
    if (t == 0) g_inv_pnorm = 1.0f / sqrtf(sh[0]);
}

// ---------------- K1: y[n] = |feat[n] . p| / ||p||  (one warp per node) -----
__global__ __launch_bounds__(256) void score_kernel(const float* __restrict__ feat,
                                                    const float* __restrict__ p,
                                                    int N) {
    int lane = threadIdx.x & 31;
    int n = (blockIdx.x * blockDim.x + threadIdx.x) >> 5;
    if (n >= N) return;
    const float4* f4 = (const float4*)(feat + (size_t)n * F);
    const float4* p4 = (const float4*)p;
    float s = 0.f;
#pragma unroll
    for (int j = 0; j < 2; j++) {
        float4 f = f4[lane * 2 + j];
        float4 q = p4[lane * 2 + j];
        s += f.x * q.x + f.y * q.y + f.z * q.z + f.w * q.w;
    }
#pragma unroll
    for (int off = 16; off; off >>= 1)
        s += __shfl_xor_sync(0xffffffffu, s, off);
    if (lane == 0) g_y[n] = fabsf(s) * g_inv_pnorm;
}

// ---------------- K2: ft = gate(y) * (feat @ W)  -----------------------------
// 64x64 tile, 256 threads as 16x16, 4x4 microtile, packed f32x2 FMAs.
#define BM 64
#define BN 64
#define BK 16
__global__ __launch_bounds__(256) void gemm_kernel(const float* __restrict__ feat,
                                                   const float* __restrict__ W,
                                                   int N) {
    __shared__ __align__(16) float As[BK][BM + 4];   // stride 68 floats = 272B (16B aligned rows)
    __shared__ __align__(16) float Ws[BK][BN];
    int t  = threadIdx.x;
    int tx = t & 15;        // 0..15 -> 4 cols each
    int ty = t >> 4;        // 0..15 -> 4 rows each
    int m0 = blockIdx.y * BM;
    int n0 = blockIdx.x * BN;

    unsigned long long acc[4][2];
#pragma unroll
    for (int i = 0; i < 4; i++) { acc[i][0] = 0ull; acc[i][1] = 0ull; }

    // A-load mapping: r = t/4 (row 0..63), c4 = (t&3)*4 (k offset)
    int ar = t >> 2;
    int ac = (t & 3) << 2;
    // W-load mapping: kk = t/16, cc = (t&15)*4
    int wk = t >> 4;
    int wc = (t & 15) << 2;

    for (int k0 = 0; k0 < F; k0 += BK) {
        float4 a4 = make_float4(0.f, 0.f, 0.f, 0.f);
        int m = m0 + ar;
        if (m < N) a4 = *(const float4*)&feat[(size_t)m * F + k0 + ac];
        float4 w4 = *(const float4*)&W[(size_t)(k0 + wk) * HO + n0 + wc];

        __syncthreads();
        As[ac + 0][ar] = a4.x;
        As[ac + 1][ar] = a4.y;
        As[ac + 2][ar] = a4.z;
        As[ac + 3][ar] = a4.w;
        *(float4*)&Ws[wk][wc] = w4;
        __syncthreads();

#pragma unroll
        for (int k = 0; k < BK; k++) {
            float4 av = *(const float4*)&As[k][ty << 2];
            ulonglong2 bv = *(const ulonglong2*)&Ws[k][tx << 2];
            unsigned long long a0 = pack2(av.x);
            unsigned long long a1 = pack2(av.y);
            unsigned long long a2 = pack2(av.z);
            unsigned long long a3 = pack2(av.w);
            acc[0][0] = ffma2(a0, bv.x, acc[0][0]);
            acc[0][1] = ffma2(a0, bv.y, acc[0][1]);
            acc[1][0] = ffma2(a1, bv.x, acc[1][0]);
            acc[1][1] = ffma2(a1, bv.y, acc[1][1]);
            acc[2][0] = ffma2(a2, bv.x, acc[2][0]);
            acc[2][1] = ffma2(a2, bv.y, acc[2][1]);
            acc[3][0] = ffma2(a3, bv.x, acc[3][0]);
            acc[3][1] = ffma2(a3, bv.y, acc[3][1]);
        }
    }

    // epilogue: apply gate = 2*sigmoid(y[m]) per row, store
#pragma unroll
    for (int i = 0; i < 4; i++) {
        int m = m0 + (ty << 2) + i;
        if (m >= N) continue;
        float gate = 2.0f / (1.0f + expf(-g_y[m]));
        float2 lo = unpack2(acc[i][0]);
        float2 hi = unpack2(acc[i][1]);
        float4 o = make_float4(lo.x * gate, lo.y * gate, hi.x * gate, hi.y * gate);
        *(float4*)&g_ft[(size_t)m * HO + n0 + (tx << 2)] = o;
    }
}

// ---------------- K2b: el/er per (node, head) --------------------------------
__global__ __launch_bounds__(256) void elr_kernel(const float* __restrict__ attn_l,
                                                  const float* __restrict__ attn_r,
                                                  int N) {
    int t = blockIdx.x * blockDim.x + threadIdx.x;
    if (t >= N * H) return;
    int n = t >> 3;
    int h = t & 7;
    const float4* f4  = (const float4*)(g_ft + (size_t)n * HO + h * O);
    const float4* al4 = (const float4*)(attn_l + h * O);
    const float4* ar4 = (const float4*)(attn_r + h * O);
    float sl = 0.f, sr = 0.f;
#pragma unroll
    for (int j = 0; j < O / 4; j++) {
        float4 f = f4[j];
        float4 a = al4[j];
        float4 b = ar4[j];
        sl += f.x * a.x + f.y * a.y + f.z * a.z + f.w * a.w;
        sr += f.x * b.x + f.y * b.y + f.z * b.z + f.w * b.w;
    }
    g_el[t] = sl;
    g_er[t] = sr;
}

// ---------------- K3: top-8, edge softmax, gather-aggregate, ELU -------------
// One warp per destination node.
__global__ __launch_bounds__(256) void agg_kernel(const int* __restrict__ nbr,
                                                  float* __restrict__ out,
                                                  int N) {
    __shared__ int ssrc[8][KSEL];   // 8 warps per block
    int lane = threadIdx.x & 31;
    int wid  = threadIdx.x >> 5;
    int n = (blockIdx.x * blockDim.x + threadIdx.x) >> 5;
    if (n >= N) return;

    // load 64 neighbor ids + their scores (2 per lane)
    int id0 = nbr[(size_t)n * D + lane];
    int id1 = nbr[(size_t)n * D + 32 + lane];
    float v0 = __ldg(&g_y[id0]);
    float v1 = __ldg(&g_y[id1]);
    bool m0 = false, m1 = false;

    // iterative top-8 argmax (smaller slot index wins ties -> matches lax.top_k)
#pragma unroll
    for (int it = 0; it < KSEL; it++) {
        float bv = m0 ? -3.402823466e38f : v0;
        int   bi = lane;
        float c1 = m1 ? -3.402823466e38f : v1;
        if (c1 > bv) { bv = c1; bi = lane + 32; }
#pragma unroll
        for (int off = 16; off; off >>= 1) {
            float ov = __shfl_xor_sync(0xffffffffu, bv, off);
            int   oi = __shfl_xor_sync(0xffffffffu, bi, off);
            if (ov > bv || (ov == bv && oi < bi)) { bv = ov; bi = oi; }
        }
        int sid = (bi < 32) ? __shfl_sync(0xffffffffu, id0, bi)
                            : __shfl_sync(0xffffffffu, id1, bi - 32);
        if (lane == it) ssrc[wid][it] = sid;
        if (bi == lane)      m0 = true;
        else if (bi == lane + 32) m1 = true;
    }
    __syncwarp();

    // edge scores + softmax over k.  lane -> (ka = lane>>3 handles k and k+4, h = lane&7)
    int h  = lane & 7;
    int ka = lane >> 3;
    float erh = g_er[n * H + h];
    int sa = ssrc[wid][ka];
    int sb = ssrc[wid][ka + 4];
    float ea = g_el[sa * H + h] + erh;
    float eb = g_el[sb * H + h] + erh;
    ea = (ea > 0.f) ? ea : NEG_SLOPE * ea;
    eb = (eb > 0.f) ? eb : NEG_SLOPE * eb;
    float mx = fmaxf(ea, eb);
    mx = fmaxf(mx, __shfl_xor_sync(0xffffffffu, mx, 8));
    mx = fmaxf(mx, __shfl_xor_sync(0xffffffffu, mx, 16));
    float xa = expf(ea - mx);
    float xb = expf(eb - mx);
    float s = xa + xb;
    s += __shfl_xor_sync(0xffffffffu, s, 8);
    s += __shfl_xor_sync(0xffffffffu, s, 16);
    float inv = 1.0f / s;
    xa *= inv;   // a[ka][h]
    xb *= inv;   // a[ka+4][h]

    // aggregation: lane owns 8 contiguous output cols [lane*8, lane*8+8) -> head lane>>2
    int hout = lane >> 2;
    float acc0 = 0.f, acc1 = 0.f, acc2 = 0.f, acc3 = 0.f;
    float acc4 = 0.f, acc5 = 0.f, acc6 = 0.f, acc7 = 0.f;
#pragma unroll
    for (int k = 0; k < KSEL; k++) {
        float ak = __shfl_sync(0xffffffffu, (k < 4) ? xa : xb, ((k & 3) << 3) | hout);
        int sk = ssrc[wid][k];
        const float4* row = (const float4*)(g_ft + (size_t)sk * HO) + lane * 2;
        float4 u = __ldg(&row[0]);
        float4 w = __ldg(&row[1]);
        acc0 += ak * u.x; acc1 += ak * u.y; acc2 += ak * u.z; acc3 += ak * u.w;
        acc4 += ak * w.x; acc5 += ak * w.y; acc6 += ak * w.z; acc7 += ak * w.w;
    }

    // ELU + store
    float4 o1, o2;
    o1.x = acc0 > 0.f ? acc0 : expm1f(acc0);
    o1.y = acc1 > 0.f ? acc1 : expm1f(acc1);
    o1.z = acc2 > 0.f ? acc2 : expm1f(acc2);
    o1.w = acc3 > 0.f ? acc3 : expm1f(acc3);
    o2.x = acc4 > 0.f ? acc4 : expm1f(acc4);
    o2.y = acc5 > 0.f ? acc5 : expm1f(acc5);
    o2.z = acc6 > 0.f ? acc6 : expm1f(acc6);
    o2.w = acc7 > 0.f ? acc7 : expm1f(acc7);
    float4* op = (float4*)(out + (size_t)n * HO) + lane * 2;
    op[0] = o1;
    op[1] = o2;
}

// ---------------- launch ------------------------------------------------------
extern "C" void kernel_launch(void* const* d_in, const int* in_sizes, int n_in,
                              void* d_out, int out_size) {
    const float* feat   = (const float*)d_in[0];
    const int*   nbr    = (const int*)d_in[1];
    const float* p      = (const float*)d_in[2];
    const float* W      = (const float*)d_in[3];
    const float* attn_l = (const float*)d_in[4];
    const float* attn_r = (const float*)d_in[5];
    float* out = (float*)d_out;

    int Fdim = in_sizes[2];            // 256
    int N = in_sizes[0] / Fdim;        // 50000

    pnorm_kernel<<<1, 256>>>(p);
    score_kernel<<<(N + 7) / 8, 256>>>(feat, p, N);
    dim3 g2(HO / BN, (N + BM - 1) / BM);
    gemm_kernel<<<g2, 256>>>(feat, W, N);
    elr_kernel<<<(N * H + 255) / 256, 256>>>(attn_l, attn_r, N);
    agg_kernel<<<(N + 7) / 8, 256>>>(nbr, out, N);
}